// round 5
// baseline (speedup 1.0000x reference)
#include <cuda_runtime.h>
#include <cstddef>

#define BB 2
#define TT 2048
#define DD 1024
#define HH 16
#define HD 64

// Scratch (device globals: allocation-free per harness rules)
__device__ float g_q[BB*HH*TT*HD];   // (b,h,t,d)
__device__ float g_k[BB*HH*TT*HD];   // (b,h,t,d)
__device__ float g_v[BB*HH*TT*HD];   // (b,h,t,d)
__device__ float g_y[BB*TT*HH*HD];   // (b,t,h,d)

// exp on the FMA pipe (no MUFU): exp(x) = 2^(x*log2e), degree-5 Taylor of 2^f,
// exponent spliced via int bits. |rel err| ~8e-5, valid for x <= 0 (clamped).
__device__ __forceinline__ float fast_exp(float x) {
    float t = x * 1.4426950408889634f;
    t = fmaxf(t, -126.0f);
    float fi = floorf(t);
    float f = t - fi;
    float p = 1.3333558e-3f;
    p = fmaf(p, f, 9.6181291e-3f);
    p = fmaf(p, f, 5.5504109e-2f);
    p = fmaf(p, f, 2.4022651e-1f);
    p = fmaf(p, f, 6.9314718e-1f);
    p = fmaf(p, f, 1.0f);
    return p * __int_as_float(((int)fi + 127) << 23);
}

// ---------------------------------------------------------------------------
// Kernel 1: qk = x_norm @ qk_w^T + qk_b, scattered into g_q/g_k (b,h,t,d).
// C[M=4096][N=2048], K=1024. 128x128x16 tiles, 256 threads, 8x8 microtile
// (split as 2x2 blocks of 4 for conflict-free float4 smem frags).
// ---------------------------------------------------------------------------
__global__ __launch_bounds__(256, 2)
void qk_proj_kernel(const float* __restrict__ A, const float* __restrict__ W,
                    const float* __restrict__ bias) {
    __shared__ float As[16][128];
    __shared__ float Ws[16][128];
    const int bn = blockIdx.x * 128;
    const int bm = blockIdx.y * 128;
    const int tid = threadIdx.x;
    const int rm = tid >> 4;   // 0..15
    const int cn = tid & 15;   // 0..15

    float acc[8][8];
    #pragma unroll
    for (int i = 0; i < 8; i++)
        #pragma unroll
        for (int j = 0; j < 8; j++) acc[i][j] = 0.f;

    for (int k0 = 0; k0 < DD; k0 += 16) {
        #pragma unroll
        for (int it = 0; it < 2; it++) {
            int idx = tid + it * 256;        // 0..511
            int row = idx & 127;
            int kk  = (idx >> 7) * 4;        // 0,4,8,12
            float4 va = *(const float4*)(A + (size_t)(bm + row) * DD + k0 + kk);
            As[kk+0][row] = va.x; As[kk+1][row] = va.y;
            As[kk+2][row] = va.z; As[kk+3][row] = va.w;
            float4 vw = *(const float4*)(W + (size_t)(bn + row) * DD + k0 + kk);
            Ws[kk+0][row] = vw.x; Ws[kk+1][row] = vw.y;
            Ws[kk+2][row] = vw.z; Ws[kk+3][row] = vw.w;
        }
        __syncthreads();
        #pragma unroll
        for (int kk = 0; kk < 16; kk++) {
            float a[8], w[8];
            *(float4*)&a[0] = *(const float4*)&As[kk][rm * 4];
            *(float4*)&a[4] = *(const float4*)&As[kk][64 + rm * 4];
            *(float4*)&w[0] = *(const float4*)&Ws[kk][cn * 4];
            *(float4*)&w[4] = *(const float4*)&Ws[kk][64 + cn * 4];
            #pragma unroll
            for (int i = 0; i < 8; i++)
                #pragma unroll
                for (int j = 0; j < 8; j++)
                    acc[i][j] = fmaf(a[i], w[j], acc[i][j]);
        }
        __syncthreads();
    }

    // Epilogue: +bias, scatter to q/k in (b,h,t,d) layout. 8-col groups never
    // cross a 64 (head) or 1024 (q/k) boundary since bn,64-blocks align.
    #pragma unroll
    for (int jh = 0; jh < 2; jh++) {
        int n0 = bn + jh * 64 + cn * 4;
        float4 bv = *(const float4*)(bias + n0);
        int nn = n0 & (DD - 1);
        int hh = nn >> 6, dd = nn & 63;
        float* base = (n0 < DD) ? g_q : g_k;
        #pragma unroll
        for (int ih = 0; ih < 2; ih++) {
            #pragma unroll
            for (int i = 0; i < 4; i++) {
                int m = bm + ih * 64 + rm * 4 + i;
                int b = m >> 11, t = m & (TT - 1);
                float4 o;
                o.x = acc[ih*4+i][jh*4+0] + bv.x;
                o.y = acc[ih*4+i][jh*4+1] + bv.y;
                o.z = acc[ih*4+i][jh*4+2] + bv.z;
                o.w = acc[ih*4+i][jh*4+3] + bv.w;
                *(float4*)(base + ((size_t)((b*HH + hh)*TT + t)) * HD + dd) = o;
            }
        }
    }
}

// ---------------------------------------------------------------------------
// Kernel 2/4: head-mix einsum. mode 0: v[b,i,t,d] = sum_j xt[b,t,j,d]*vf[i,j]
// (scatter into g_v). mode 1: out[b,t,i,d] = sum_j g_y[b,t,j,d]*of[i,j]
// (contiguous into d_out). One block per (b,t) row, memory-bound.
// ---------------------------------------------------------------------------
__global__ __launch_bounds__(256)
void mix_kernel(const float* __restrict__ src, const float* __restrict__ fact,
                float* __restrict__ dst, int mode) {
    __shared__ float xs[1024];
    __shared__ float fs[256];
    const int bt = blockIdx.x;         // b*T + t
    const int tid = threadIdx.x;
    const float* s = (mode == 0) ? src : g_y;
    *(float4*)&xs[tid * 4] = *(const float4*)(s + (size_t)bt * 1024 + tid * 4);
    if (tid < 64) *(float4*)&fs[tid * 4] = *(const float4*)(fact + tid * 4);
    __syncthreads();

    const int o = tid * 4;
    const int i = o >> 6, d = o & 63;
    float4 acc = make_float4(0.f, 0.f, 0.f, 0.f);
    #pragma unroll
    for (int j = 0; j < 16; j++) {
        float f = fs[i * 16 + j];
        float4 x = *(const float4*)&xs[j * 64 + d];
        acc.x = fmaf(f, x.x, acc.x); acc.y = fmaf(f, x.y, acc.y);
        acc.z = fmaf(f, x.z, acc.z); acc.w = fmaf(f, x.w, acc.w);
    }
    if (mode == 0) {
        int b = bt >> 11, t = bt & (TT - 1);
        *(float4*)(g_v + ((size_t)(b*HH + i)*TT + t) * HD + d) = acc;
    } else {
        *(float4*)(dst + (size_t)bt * 1024 + o) = acc;
    }
}

// ---------------------------------------------------------------------------
// Kernel 3: causal flash attention with ALiBi, fp32.
// Block = one (b,h) x one 64-row q-tile; each block processes the work-balanced
// pair (qt, 31-qt). 256 threads, 4x4 microtiles for both 64^3 GEMM phases.
// smem: Qs[d][r], KPs (K as [d][c], then P as [c][r] XOR-swizzled), Vs[c][d].
// Exactly 48KB static shared.
// ---------------------------------------------------------------------------
__global__ __launch_bounds__(256)
void attn_kernel() {
    __shared__ float Qs[64][64];
    __shared__ float KPs[64][64];
    __shared__ float Vs[64][64];

    const int bh = blockIdx.y;
    const int h = bh & (HH - 1);
    const float slope = exp2f(-0.5f * (float)(h + 1));   // H=16 pow2 slopes
    const float* Q = g_q + (size_t)bh * TT * HD;
    const float* K = g_k + (size_t)bh * TT * HD;
    const float* V = g_v + (size_t)bh * TT * HD;
    const int tid = threadIdx.x;
    const int tr = tid >> 4;   // row group 0..15 (rows tr*4..tr*4+3)
    const int tc = tid & 15;   // col group 0..15

    for (int rep = 0; rep < 2; rep++) {
        const int qt = rep ? (31 - (int)blockIdx.x) : (int)blockIdx.x;
        __syncthreads();
        // Load Q tile transposed: Qs[d][r]
        #pragma unroll
        for (int it = 0; it < 4; it++) {
            int idx = tid + it * 256;       // 0..1023
            int r = idx >> 4;
            int dd = (idx & 15) * 4;
            float4 v = *(const float4*)(Q + (size_t)(qt*64 + r) * HD + dd);
            Qs[dd+0][r] = v.x; Qs[dd+1][r] = v.y;
            Qs[dd+2][r] = v.z; Qs[dd+3][r] = v.w;
        }

        float O[4][4];
        float m_i[4], l_i[4];
        #pragma unroll
        for (int i = 0; i < 4; i++) {
            m_i[i] = -1e30f; l_i[i] = 0.f;
            #pragma unroll
            for (int j = 0; j < 4; j++) O[i][j] = 0.f;
        }

        for (int kt = 0; kt <= qt; kt++) {
            __syncthreads();   // prev PV reads + Qs load complete
            #pragma unroll
            for (int it = 0; it < 4; it++) {
                int idx = tid + it * 256;
                int c = idx >> 4;
                int dd = (idx & 15) * 4;
                float4 kv = *(const float4*)(K + (size_t)(kt*64 + c) * HD + dd);
                KPs[dd+0][c] = kv.x; KPs[dd+1][c] = kv.y;
                KPs[dd+2][c] = kv.z; KPs[dd+3][c] = kv.w;
                *(float4*)&Vs[c][dd] =
                    *(const float4*)(V + (size_t)(kt*64 + c) * HD + dd);
            }
            __syncthreads();

            // S = Q K^T (4x4 per thread)
            float s[4][4];
            #pragma unroll
            for (int i = 0; i < 4; i++)
                #pragma unroll
                for (int j = 0; j < 4; j++) s[i][j] = 0.f;
            #pragma unroll 8
            for (int k = 0; k < 64; k++) {
                float qv[4], kv[4];
                *(float4*)qv = *(const float4*)&Qs[k][tr * 4];
                *(float4*)kv = *(const float4*)&KPs[k][tc * 4];
                #pragma unroll
                for (int i = 0; i < 4; i++)
                    #pragma unroll
                    for (int j = 0; j < 4; j++)
                        s[i][j] = fmaf(qv[i], kv[j], s[i][j]);
            }

            // scale + ALiBi bias + causal mask (only diagonal tile can mask)
            const bool diag = (kt == qt);
            #pragma unroll
            for (int i = 0; i < 4; i++) {
                int qi = qt * 64 + tr * 4 + i;
                #pragma unroll
                for (int j = 0; j < 4; j++) {
                    int ki = kt * 64 + tc * 4 + j;
                    float v = fmaf(s[i][j], 0.125f, slope * (float)(ki - qi));
                    s[i][j] = (diag && ki > qi) ? -1e30f : v;
                }
            }
            __syncthreads();   // all K reads done before P overwrites KPs

            // online softmax (row stats reduced over the 16 threads of a row
            // group, which are 16 consecutive lanes -> shfl_xor 8/4/2/1)
            #pragma unroll
            for (int i = 0; i < 4; i++) {
                float tmax = fmaxf(fmaxf(s[i][0], s[i][1]),
                                   fmaxf(s[i][2], s[i][3]));
                #pragma unroll
                for (int off = 8; off >= 1; off >>= 1)
                    tmax = fmaxf(tmax, __shfl_xor_sync(0xffffffffu, tmax, off));
                float mnew = fmaxf(m_i[i], tmax);
                float alpha = fast_exp(m_i[i] - mnew);
                float rsum = 0.f;
                #pragma unroll
                for (int j = 0; j < 4; j++) {
                    float p = fast_exp(s[i][j] - mnew);
                    s[i][j] = p;
                    rsum += p;
                }
                #pragma unroll
                for (int off = 8; off >= 1; off >>= 1)
                    rsum += __shfl_xor_sync(0xffffffffu, rsum, off);
                l_i[i] = l_i[i] * alpha + rsum;
                m_i[i] = mnew;
                #pragma unroll
                for (int j = 0; j < 4; j++) O[i][j] *= alpha;
            }

            // store P as [c][r], row-group XOR-swizzled (g = tr ^ c_group) to
            // break the stride-256B same-bank pattern (16-way -> 4-way)
            #pragma unroll
            for (int j = 0; j < 4; j++) {
                int c = tc * 4 + j;
                int g = (tr ^ tc) & 15;    // c>>2 == tc
                #pragma unroll
                for (int i = 0; i < 4; i++)
                    KPs[c][g * 4 + i] = s[i][j];
            }
            __syncthreads();

            // O += P V (4x4 per thread)
            #pragma unroll 8
            for (int c = 0; c < 64; c++) {
                float pv[4], vv[4];
                int g = (tr ^ (c >> 2)) & 15;
                *(float4*)pv = *(const float4*)&KPs[c][g * 4];
                *(float4*)vv = *(const float4*)&Vs[c][tc * 4];
                #pragma unroll
                for (int i = 0; i < 4; i++)
                    #pragma unroll
                    for (int j = 0; j < 4; j++)
                        O[i][j] = fmaf(pv[i], vv[j], O[i][j]);
            }
        }

        // epilogue: normalize, write g_y in (b,t,h,d)
        const int b = bh >> 4;
        #pragma unroll
        for (int i = 0; i < 4; i++) {
            int qi = qt * 64 + tr * 4 + i;
            float inv = 1.0f / l_i[i];
            float4 o;
            o.x = O[i][0] * inv; o.y = O[i][1] * inv;
            o.z = O[i][2] * inv; o.w = O[i][3] * inv;
            *(float4*)(g_y + ((size_t)((b*TT + qi)*HH + h)) * HD + tc * 4) = o;
        }
    }
}

// ---------------------------------------------------------------------------
extern "C" void kernel_launch(void* const* d_in, const int* in_sizes, int n_in,
                              void* d_out, int out_size) {
    const float* x_norm   = (const float*)d_in[0];
    const float* xt       = (const float*)d_in[1];
    const float* qk_w     = (const float*)d_in[2];
    const float* qk_b     = (const float*)d_in[3];
    const float* v_fact   = (const float*)d_in[4];
    const float* out_fact = (const float*)d_in[5];
    float* out = (float*)d_out;

    qk_proj_kernel<<<dim3(DD*2/128, BB*TT/128), 256>>>(x_norm, qk_w, qk_b);
    mix_kernel<<<BB*TT, 256>>>(xt, v_fact, nullptr, 0);
    attn_kernel<<<dim3(16, BB*HH), 256>>>();
    mix_kernel<<<BB*TT, 256>>>(nullptr, out_fact, out, 1);
}

// round 6
// speedup vs baseline: 2.3219x; 2.3219x over previous
#include <cuda_runtime.h>
#include <cuda_bf16.h>
#include <cstdint>
#include <cstddef>

#define BB 2
#define TT 2048
#define DD 1024
#define HH 16
#define HD 64

// ---- global scratch (allocation-free) ----
__device__ __align__(16) uint32_t g_ah[512*4096];   // x_norm packed hi [k2][m]
__device__ __align__(16) uint32_t g_al[512*4096];
__device__ __align__(16) uint32_t g_wh[512*2048];   // qk_w packed hi  [k2][n]
__device__ __align__(16) uint32_t g_wl[512*2048];
__device__ __align__(16) uint32_t g_qh[32*32*2048]; // q packed [bh][d2][t]
__device__ __align__(16) uint32_t g_ql[32*32*2048];
__device__ __align__(16) uint32_t g_kh[32*32*2048]; // k packed [bh][d2][t]
__device__ __align__(16) uint32_t g_kl[32*32*2048];
__device__ __align__(16) uint32_t g_vh[32*1024*64]; // v packed [bh][t2][d]
__device__ __align__(16) uint32_t g_vl[32*1024*64];
__device__ __align__(16) float    g_y[BB*TT*HH*HD]; // (b,t,h,d)

__device__ __forceinline__ float fast_exp(float x) {
    float t = x * 1.4426950408889634f;
    t = fmaxf(t, -126.0f);
    float fi = floorf(t);
    float f = t - fi;
    float p = 1.3333558e-3f;
    p = fmaf(p, f, 9.6181291e-3f);
    p = fmaf(p, f, 5.5504109e-2f);
    p = fmaf(p, f, 2.4022651e-1f);
    p = fmaf(p, f, 6.9314718e-1f);
    p = fmaf(p, f, 1.0f);
    return p * __int_as_float(((int)fi + 127) << 23);
}

__device__ __forceinline__ uint32_t pk2(float f0, float f1) {
    __nv_bfloat162 h = __floats2bfloat162_rn(f0, f1);
    return *reinterpret_cast<uint32_t*>(&h);
}
__device__ __forceinline__ void split2(float f0, float f1,
                                       uint32_t& hi, uint32_t& lo) {
    float h0 = __bfloat162float(__float2bfloat16(f0));
    float h1 = __bfloat162float(__float2bfloat16(f1));
    hi = pk2(h0, h1);
    lo = pk2(f0 - h0, f1 - h1);
}
__device__ __forceinline__ void mma_bf16(float* c, const uint32_t* a,
                                         uint32_t b0, uint32_t b1) {
    asm volatile(
        "mma.sync.aligned.m16n8k16.row.col.f32.bf16.bf16.f32 "
        "{%0,%1,%2,%3}, {%4,%5,%6,%7}, {%8,%9}, {%0,%1,%2,%3};\n"
        : "+f"(c[0]), "+f"(c[1]), "+f"(c[2]), "+f"(c[3])
        : "r"(a[0]), "r"(a[1]), "r"(a[2]), "r"(a[3]), "r"(b0), "r"(b1));
}

// ---------------------------------------------------------------------------
// pack fp32 [M][1024] -> hi/lo k-pair-packed [512][M] (transposed)
// ---------------------------------------------------------------------------
__global__ __launch_bounds__(256)
void pack_kernel(const float* __restrict__ A, uint32_t* __restrict__ Oh,
                 uint32_t* __restrict__ Ol, int M) {
    __shared__ uint32_t shh[32][33];
    __shared__ uint32_t shl[32][33];
    const int bk2 = blockIdx.x * 32;
    const int bm  = blockIdx.y * 32;
    const int tid = threadIdx.x;
    #pragma unroll
    for (int it = 0; it < 2; it++) {
        int idx = tid + it * 256;
        int row = idx >> 4, c4 = idx & 15;
        float4 v = *(const float4*)(A + (size_t)(bm + row) * 1024 + bk2*2 + c4*4);
        uint32_t h, l;
        split2(v.x, v.y, h, l); shh[c4*2][row] = h;   shl[c4*2][row] = l;
        split2(v.z, v.w, h, l); shh[c4*2+1][row] = h; shl[c4*2+1][row] = l;
    }
    __syncthreads();
    #pragma unroll
    for (int it = 0; it < 2; it++) {
        int idx = tid + it * 256;
        int r = idx >> 4, m2 = (idx & 15) * 2;
        *(uint2*)(Oh + (size_t)(bk2 + r) * M + bm + m2) =
            make_uint2(shh[r][m2], shh[r][m2+1]);
        *(uint2*)(Ol + (size_t)(bk2 + r) * M + bm + m2) =
            make_uint2(shl[r][m2], shl[r][m2+1]);
    }
}

// ---------------------------------------------------------------------------
// qk projection bf16x3 mma. C[4096][2048], K=1024. 128x128 tiles, 8 warps
// (4x2), warp m32xn64. Epilogue: +bias, split, scatter to g_q/g_k [bh][d2][t].
// ---------------------------------------------------------------------------
__global__ __launch_bounds__(256)
void qk_proj_mma(const float* __restrict__ bias) {
    __shared__ uint32_t Ah[16][136], Al[16][136];
    __shared__ uint32_t Bh[16][136], Bl[16][136];
    const int nb = blockIdx.x, mb = blockIdx.y;
    const int tid = threadIdx.x, lane = tid & 31, wid = tid >> 5;
    const int wm = (wid & 3) * 32, wn = (wid >> 2) * 64;
    const int lq = lane & 3, lr = lane >> 2;

    float acc[2][8][4] = {};

    for (int ki = 0; ki < 32; ki++) {
        const int k2b = ki * 16;
        __syncthreads();
        #pragma unroll
        for (int it = 0; it < 2; it++) {
            int idx = tid + it * 256;
            int r = idx >> 5, c4 = idx & 31;
            size_t ga = (size_t)(k2b + r) * 4096 + mb * 128 + c4 * 4;
            size_t gb = (size_t)(k2b + r) * 2048 + nb * 128 + c4 * 4;
            *(uint4*)&Ah[r][c4*4] = *(const uint4*)(g_ah + ga);
            *(uint4*)&Al[r][c4*4] = *(const uint4*)(g_al + ga);
            *(uint4*)&Bh[r][c4*4] = *(const uint4*)(g_wh + gb);
            *(uint4*)&Bl[r][c4*4] = *(const uint4*)(g_wl + gb);
        }
        __syncthreads();
        #pragma unroll
        for (int ks = 0; ks < 2; ks++) {
            const int kb = ks * 8;
            uint32_t ah[2][4], al_[2][4];
            #pragma unroll
            for (int mi = 0; mi < 2; mi++) {
                int rb = wm + mi * 16;
                ah[mi][0]  = Ah[kb+lq][rb+lr];   ah[mi][1]  = Ah[kb+lq][rb+8+lr];
                ah[mi][2]  = Ah[kb+4+lq][rb+lr]; ah[mi][3]  = Ah[kb+4+lq][rb+8+lr];
                al_[mi][0] = Al[kb+lq][rb+lr];   al_[mi][1] = Al[kb+lq][rb+8+lr];
                al_[mi][2] = Al[kb+4+lq][rb+lr]; al_[mi][3] = Al[kb+4+lq][rb+8+lr];
            }
            #pragma unroll
            for (int ni = 0; ni < 8; ni++) {
                int cb = wn + ni * 8 + lr;
                uint32_t bh0 = Bh[kb+lq][cb],   bh1 = Bh[kb+4+lq][cb];
                uint32_t bl0 = Bl[kb+lq][cb],   bl1 = Bl[kb+4+lq][cb];
                #pragma unroll
                for (int mi = 0; mi < 2; mi++) {
                    mma_bf16(acc[mi][ni], ah[mi],  bh0, bh1);
                    mma_bf16(acc[mi][ni], ah[mi],  bl0, bl1);
                    mma_bf16(acc[mi][ni], al_[mi], bh0, bh1);
                }
            }
        }
    }

    #pragma unroll
    for (int mi = 0; mi < 2; mi++) {
        int m0 = mb * 128 + wm + mi * 16 + lr;
        int b = m0 >> 11, t = m0 & (TT - 1);
        #pragma unroll
        for (int ni = 0; ni < 8; ni++) {
            int n0 = nb * 128 + wn + ni * 8 + 2 * lq;
            float2 bv = *(const float2*)(bias + n0);
            int nn = n0 & (DD - 1);
            uint32_t* dh = (n0 < DD) ? g_qh : g_kh;
            uint32_t* dl = (n0 < DD) ? g_ql : g_kl;
            size_t base =
                ((size_t)((b*HH + (nn >> 6)) * 32 + ((nn & 63) >> 1))) * TT + t;
            uint32_t h, l;
            split2(acc[mi][ni][0] + bv.x, acc[mi][ni][1] + bv.y, h, l);
            dh[base] = h; dl[base] = l;
            split2(acc[mi][ni][2] + bv.x, acc[mi][ni][3] + bv.y, h, l);
            dh[base + 8] = h; dl[base + 8] = l;     // row+8 -> t+8
        }
    }
}

// ---------------------------------------------------------------------------
// v head-mix -> key-pair-packed hi/lo v [bh][t2][d]. Block per (b, t-pair).
// ---------------------------------------------------------------------------
__global__ __launch_bounds__(256)
void mixv_kernel(const float* __restrict__ xt, const float* __restrict__ vf) {
    __shared__ float xs[2048];
    __shared__ float fs[256];
    const int bx = blockIdx.x;
    const int b = bx >> 10, tt2 = bx & 1023;
    const int tid = threadIdx.x;
    size_t row0 = ((size_t)(b * TT + tt2 * 2)) * DD;
    *(float4*)&xs[tid*4]        = *(const float4*)(xt + row0 + tid*4);
    *(float4*)&xs[1024 + tid*4] = *(const float4*)(xt + row0 + DD + tid*4);
    if (tid < 64) *(float4*)&fs[tid*4] = *(const float4*)(vf + tid*4);
    __syncthreads();

    const int o = tid * 4, i = o >> 6, d = o & 63;
    float4 a0 = make_float4(0.f,0.f,0.f,0.f);
    float4 a1 = make_float4(0.f,0.f,0.f,0.f);
    #pragma unroll
    for (int j = 0; j < 16; j++) {
        float f = fs[i*16 + j];
        float4 x0 = *(const float4*)&xs[j*64 + d];
        float4 x1 = *(const float4*)&xs[1024 + j*64 + d];
        a0.x = fmaf(f, x0.x, a0.x); a0.y = fmaf(f, x0.y, a0.y);
        a0.z = fmaf(f, x0.z, a0.z); a0.w = fmaf(f, x0.w, a0.w);
        a1.x = fmaf(f, x1.x, a1.x); a1.y = fmaf(f, x1.y, a1.y);
        a1.z = fmaf(f, x1.z, a1.z); a1.w = fmaf(f, x1.w, a1.w);
    }
    uint4 uh, ul;
    split2(a0.x, a1.x, uh.x, ul.x);
    split2(a0.y, a1.y, uh.y, ul.y);
    split2(a0.z, a1.z, uh.z, ul.z);
    split2(a0.w, a1.w, uh.w, ul.w);
    size_t dst = ((size_t)((b*HH + i) * 1024 + tt2)) * 64 + d;
    *(uint4*)(g_vh + dst) = uh;
    *(uint4*)(g_vl + dst) = ul;
}

// ---------------------------------------------------------------------------
// causal flash attention, bf16x3 mma, ALiBi. Block = (qt, bh), q-tile 128,
// key-tile 64, 4 warps of m32xn64. P stays in registers (S frag == PV A frag).
// ---------------------------------------------------------------------------
#define ATTN_SMEM (2*32*136*4 + 4*32*72*4)

__global__ __launch_bounds__(128)
void attn_mma() {
    extern __shared__ uint32_t sm[];
    uint32_t* Qh = sm;                  // [32][136]
    uint32_t* Ql = Qh + 32*136;
    uint32_t* Kh = Ql + 32*136;         // [32][72]
    uint32_t* Kl = Kh + 32*72;
    uint32_t* Vh = Kl + 32*72;          // [32][72]
    uint32_t* Vl = Vh + 32*72;

    const int qt = 15 - (int)blockIdx.x;     // heavy tiles first
    const int bh = blockIdx.y;
    const int h = bh & (HH - 1);
    const float slope = exp2f(-0.5f * (float)(h + 1));
    const int tid = threadIdx.x, lane = tid & 31, wid = tid >> 5;
    const int lq = lane & 3, lr = lane >> 2;
    const int qbase = qt * 128, wrow = wid * 32;

    #pragma unroll
    for (int it = 0; it < 8; it++) {
        int idx = tid + it * 128;
        int r = idx >> 5, c4 = idx & 31;
        size_t g = ((size_t)(bh * 32 + r)) * TT + qbase + c4 * 4;
        *(uint4*)&Qh[r*136 + c4*4] = *(const uint4*)(g_qh + g);
        *(uint4*)&Ql[r*136 + c4*4] = *(const uint4*)(g_ql + g);
    }

    float o[2][8][4] = {};
    float m_st[2][2], l_st[2][2];
    #pragma unroll
    for (int a = 0; a < 2; a++)
        #pragma unroll
        for (int c = 0; c < 2; c++) { m_st[a][c] = -1e30f; l_st[a][c] = 0.f; }

    const int nkt = 2 * qt + 2;
    for (int kt = 0; kt < nkt; kt++) {
        __syncthreads();
        #pragma unroll
        for (int it = 0; it < 4; it++) {
            int idx = tid + it * 128;
            int r = idx >> 4, c4 = idx & 15;
            size_t gk = ((size_t)(bh * 32 + r)) * TT + kt * 64 + c4 * 4;
            *(uint4*)&Kh[r*72 + c4*4] = *(const uint4*)(g_kh + gk);
            *(uint4*)&Kl[r*72 + c4*4] = *(const uint4*)(g_kl + gk);
            size_t gv = ((size_t)(bh * 1024 + kt * 32 + r)) * 64 + c4 * 4;
            *(uint4*)&Vh[r*72 + c4*4] = *(const uint4*)(g_vh + gv);
            *(uint4*)&Vl[r*72 + c4*4] = *(const uint4*)(g_vl + gv);
        }
        __syncthreads();

        // S = Q K^T
        float s[2][8][4] = {};
        #pragma unroll
        for (int ks = 0; ks < 4; ks++) {
            int kb = ks * 8;
            uint32_t qah[2][4], qal[2][4];
            #pragma unroll
            for (int mi = 0; mi < 2; mi++) {
                int rb = wrow + mi * 16;
                qah[mi][0] = Qh[(kb+lq)*136 + rb+lr];
                qah[mi][1] = Qh[(kb+lq)*136 + rb+8+lr];
                qah[mi][2] = Qh[(kb+4+lq)*136 + rb+lr];
                qah[mi][3] = Qh[(kb+4+lq)*136 + rb+8+lr];
                qal[mi][0] = Ql[(kb+lq)*136 + rb+lr];
                qal[mi][1] = Ql[(kb+lq)*136 + rb+8+lr];
                qal[mi][2] = Ql[(kb+4+lq)*136 + rb+lr];
                qal[mi][3] = Ql[(kb+4+lq)*136 + rb+8+lr];
            }
            #pragma unroll
            for (int nj = 0; nj < 8; nj++) {
                int cb = nj * 8 + lr;
                uint32_t kh0 = Kh[(kb+lq)*72 + cb], kh1 = Kh[(kb+4+lq)*72 + cb];
                uint32_t kl0 = Kl[(kb+lq)*72 + cb], kl1 = Kl[(kb+4+lq)*72 + cb];
                #pragma unroll
                for (int mi = 0; mi < 2; mi++) {
                    mma_bf16(s[mi][nj], qah[mi], kh0, kh1);
                    mma_bf16(s[mi][nj], qah[mi], kl0, kl1);
                    mma_bf16(s[mi][nj], qal[mi], kh0, kh1);
                }
            }
        }

        // scale + ALiBi + mask + online softmax (rows per thread: mi x half)
        const bool partial = (kt >= 2 * qt);
        #pragma unroll
        for (int mi = 0; mi < 2; mi++) {
            #pragma unroll
            for (int half = 0; half < 2; half++) {
                int qi = qbase + wrow + mi * 16 + lr + half * 8;
                float tm = -1e30f;
                #pragma unroll
                for (int nj = 0; nj < 8; nj++) {
                    #pragma unroll
                    for (int c = 0; c < 2; c++) {
                        int ki = kt * 64 + nj * 8 + 2 * lq + c;
                        float v = fmaf(s[mi][nj][half*2+c], 0.125f,
                                       slope * (float)(ki - qi));
                        if (partial && ki > qi) v = -1e30f;
                        s[mi][nj][half*2+c] = v;
                        tm = fmaxf(tm, v);
                    }
                }
                tm = fmaxf(tm, __shfl_xor_sync(0xffffffffu, tm, 1));
                tm = fmaxf(tm, __shfl_xor_sync(0xffffffffu, tm, 2));
                float mnew = fmaxf(m_st[mi][half], tm);
                float alpha = fast_exp(m_st[mi][half] - mnew);
                float rsum = 0.f;
                #pragma unroll
                for (int nj = 0; nj < 8; nj++) {
                    #pragma unroll
                    for (int c = 0; c < 2; c++) {
                        float p = fast_exp(s[mi][nj][half*2+c] - mnew);
                        s[mi][nj][half*2+c] = p;
                        rsum += p;
                    }
                }
                rsum += __shfl_xor_sync(0xffffffffu, rsum, 1);
                rsum += __shfl_xor_sync(0xffffffffu, rsum, 2);
                l_st[mi][half] = l_st[mi][half] * alpha + rsum;
                m_st[mi][half] = mnew;
                #pragma unroll
                for (int nj = 0; nj < 8; nj++) {
                    o[mi][nj][half*2+0] *= alpha;
                    o[mi][nj][half*2+1] *= alpha;
                }
            }
        }

        // O += P V (P packed hi/lo from S regs; S frag layout == PV A frag)
        #pragma unroll
        for (int ks = 0; ks < 4; ks++) {
            int kb = ks * 8;
            uint32_t ph[2][4], pl[2][4];
            #pragma unroll
            for (int mi = 0; mi < 2; mi++) {
                split2(s[mi][2*ks][0],   s[mi][2*ks][1],   ph[mi][0], pl[mi][0]);
                split2(s[mi][2*ks][2],   s[mi][2*ks][3],   ph[mi][1], pl[mi][1]);
                split2(s[mi][2*ks+1][0], s[mi][2*ks+1][1], ph[mi][2], pl[mi][2]);
                split2(s[mi][2*ks+1][2], s[mi][2*ks+1][3], ph[mi][3], pl[mi][3]);
            }
            #pragma unroll
            for (int nj = 0; nj < 8; nj++) {
                int cb = nj * 8 + lr;
                uint32_t vh0 = Vh[(kb+lq)*72 + cb], vh1 = Vh[(kb+4+lq)*72 + cb];
                uint32_t vl0 = Vl[(kb+lq)*72 + cb], vl1 = Vl[(kb+4+lq)*72 + cb];
                #pragma unroll
                for (int mi = 0; mi < 2; mi++) {
                    mma_bf16(o[mi][nj], ph[mi], vh0, vh1);
                    mma_bf16(o[mi][nj], ph[mi], vl0, vl1);
                    mma_bf16(o[mi][nj], pl[mi], vh0, vh1);
                }
            }
        }
    }

    // epilogue: normalize, write g_y (b,t,h,d)
    const int b = bh >> 4;
    #pragma unroll
    for (int mi = 0; mi < 2; mi++) {
        #pragma unroll
        for (int half = 0; half < 2; half++) {
            int qi = qbase + wrow + mi * 16 + lr + half * 8;
            float inv = 1.0f / l_st[mi][half];
            #pragma unroll
            for (int nj = 0; nj < 8; nj++) {
                float2 w = make_float2(o[mi][nj][half*2] * inv,
                                       o[mi][nj][half*2+1] * inv);
                *(float2*)(g_y + ((size_t)((b*TT + qi)*HH + h))*HD
                           + nj*8 + 2*lq) = w;
            }
        }
    }
}

// ---------------------------------------------------------------------------
// final head-mix: out[b,t,i,d] = sum_j g_y[b,t,j,d]*of[i,j]
// ---------------------------------------------------------------------------
__global__ __launch_bounds__(256)
void mix_out(const float* __restrict__ fact, float* __restrict__ dst) {
    __shared__ float xs[1024];
    __shared__ float fs[256];
    const int bt = blockIdx.x;
    const int tid = threadIdx.x;
    *(float4*)&xs[tid*4] = *(const float4*)(g_y + (size_t)bt * 1024 + tid*4);
    if (tid < 64) *(float4*)&fs[tid*4] = *(const float4*)(fact + tid*4);
    __syncthreads();
    const int o = tid * 4, i = o >> 6, d = o & 63;
    float4 acc = make_float4(0.f,0.f,0.f,0.f);
    #pragma unroll
    for (int j = 0; j < 16; j++) {
        float f = fs[i*16 + j];
        float4 x = *(const float4*)&xs[j*64 + d];
        acc.x = fmaf(f, x.x, acc.x); acc.y = fmaf(f, x.y, acc.y);
        acc.z = fmaf(f, x.z, acc.z); acc.w = fmaf(f, x.w, acc.w);
    }
    *(float4*)(dst + (size_t)bt * 1024 + o) = acc;
}

// ---------------------------------------------------------------------------
extern "C" void kernel_launch(void* const* d_in, const int* in_sizes, int n_in,
                              void* d_out, int out_size) {
    const float* x_norm   = (const float*)d_in[0];
    const float* xt       = (const float*)d_in[1];
    const float* qk_w     = (const float*)d_in[2];
    const float* qk_b     = (const float*)d_in[3];
    const float* v_fact   = (const float*)d_in[4];
    const float* out_fact = (const float*)d_in[5];
    float* out = (float*)d_out;

    uint32_t *p_ah, *p_al, *p_wh, *p_wl;
    cudaGetSymbolAddress((void**)&p_ah, g_ah);
    cudaGetSymbolAddress((void**)&p_al, g_al);
    cudaGetSymbolAddress((void**)&p_wh, g_wh);
    cudaGetSymbolAddress((void**)&p_wl, g_wl);
    cudaFuncSetAttribute(attn_mma,
        cudaFuncAttributeMaxDynamicSharedMemorySize, ATTN_SMEM);

    pack_kernel<<<dim3(16, 128), 256>>>(x_norm, p_ah, p_al, 4096);
    pack_kernel<<<dim3(16, 64),  256>>>(qk_w,   p_wh, p_wl, 2048);
    mixv_kernel<<<2048, 256>>>(xt, v_fact);
    qk_proj_mma<<<dim3(16, 32), 256>>>(qk_b);
    attn_mma<<<dim3(16, 32), 128, ATTN_SMEM>>>();
    mix_out<<<BB*TT, 256>>>(out_fact, out);
}

// round 8
// speedup vs baseline: 2.8546x; 1.2294x over previous
#include <cuda_runtime.h>
#include <cuda_bf16.h>
#include <cstdint>
#include <cstddef>

#define BB 2
#define TT 2048
#define DD 1024
#define HH 16
#define HD 64

// ---- global scratch (allocation-free) ----
__device__ __align__(16) uint32_t g_ah[512*4096];   // x_norm packed hi [k2][m]
__device__ __align__(16) uint32_t g_al[512*4096];
__device__ __align__(16) uint32_t g_wh[512*2048];   // qk_w packed hi  [k2][n]
__device__ __align__(16) uint32_t g_wl[512*2048];
__device__ __align__(16) uint32_t g_qh[32*32*2048]; // q packed [bh][d2][t]
__device__ __align__(16) uint32_t g_ql[32*32*2048];
__device__ __align__(16) uint32_t g_kh[32*32*2048]; // k packed [bh][d2][t]
__device__ __align__(16) uint32_t g_kl[32*32*2048];
__device__ __align__(16) uint32_t g_vh[32*1024*64]; // v packed [bh][t2][d]
__device__ __align__(16) uint32_t g_vl[32*1024*64];
__device__ __align__(16) float    g_y[BB*TT*HH*HD]; // (b,t,h,d)

__device__ __forceinline__ float fast_exp(float x) {
    float t = x * 1.4426950408889634f;
    t = fmaxf(t, -126.0f);
    float fi = floorf(t);
    float f = t - fi;
    float p = 1.3333558e-3f;
    p = fmaf(p, f, 9.6181291e-3f);
    p = fmaf(p, f, 5.5504109e-2f);
    p = fmaf(p, f, 2.4022651e-1f);
    p = fmaf(p, f, 6.9314718e-1f);
    p = fmaf(p, f, 1.0f);
    return p * __int_as_float(((int)fi + 127) << 23);
}

__device__ __forceinline__ uint32_t pk2(float f0, float f1) {
    __nv_bfloat162 h = __floats2bfloat162_rn(f0, f1);
    return *reinterpret_cast<uint32_t*>(&h);
}
__device__ __forceinline__ void split2(float f0, float f1,
                                       uint32_t& hi, uint32_t& lo) {
    float h0 = __bfloat162float(__float2bfloat16(f0));
    float h1 = __bfloat162float(__float2bfloat16(f1));
    hi = pk2(h0, h1);
    lo = pk2(f0 - h0, f1 - h1);
}
__device__ __forceinline__ void mma_bf16(float* c, const uint32_t* a,
                                         uint32_t b0, uint32_t b1) {
    asm volatile(
        "mma.sync.aligned.m16n8k16.row.col.f32.bf16.bf16.f32 "
        "{%0,%1,%2,%3}, {%4,%5,%6,%7}, {%8,%9}, {%0,%1,%2,%3};\n"
        : "+f"(c[0]), "+f"(c[1]), "+f"(c[2]), "+f"(c[3])
        : "r"(a[0]), "r"(a[1]), "r"(a[2]), "r"(a[3]), "r"(b0), "r"(b1));
}
__device__ __forceinline__ void cp16(uint32_t* sdst, const uint32_t* gsrc) {
    uint32_t sa = (uint32_t)__cvta_generic_to_shared(sdst);
    asm volatile("cp.async.cg.shared.global [%0], [%1], 16;\n"
                 :: "r"(sa), "l"(gsrc));
}
#define CP_COMMIT() asm volatile("cp.async.commit_group;\n" ::: "memory")
#define CP_WAIT1()  asm volatile("cp.async.wait_group 1;\n" ::: "memory")
#define CP_WAIT0()  asm volatile("cp.async.wait_group 0;\n" ::: "memory")

// ---------------------------------------------------------------------------
// pack fp32 [M][1024] -> hi/lo k-pair-packed [512][M] (transposed)
// ---------------------------------------------------------------------------
__global__ __launch_bounds__(256)
void pack_kernel(const float* __restrict__ A, uint32_t* __restrict__ Oh,
                 uint32_t* __restrict__ Ol, int M) {
    __shared__ uint32_t shh[32][33];
    __shared__ uint32_t shl[32][33];
    const int bk2 = blockIdx.x * 32;
    const int bm  = blockIdx.y * 32;
    const int tid = threadIdx.x;
    #pragma unroll
    for (int it = 0; it < 2; it++) {
        int idx = tid + it * 256;
        int row = idx >> 4, c4 = idx & 15;
        float4 v = *(const float4*)(A + (size_t)(bm + row) * 1024 + bk2*2 + c4*4);
        uint32_t h, l;
        split2(v.x, v.y, h, l); shh[c4*2][row] = h;   shl[c4*2][row] = l;
        split2(v.z, v.w, h, l); shh[c4*2+1][row] = h; shl[c4*2+1][row] = l;
    }
    __syncthreads();
    #pragma unroll
    for (int it = 0; it < 2; it++) {
        int idx = tid + it * 256;
        int r = idx >> 4, m2 = (idx & 15) * 2;
        *(uint2*)(Oh + (size_t)(bk2 + r) * M + bm + m2) =
            make_uint2(shh[r][m2], shh[r][m2+1]);
        *(uint2*)(Ol + (size_t)(bk2 + r) * M + bm + m2) =
            make_uint2(shl[r][m2], shl[r][m2+1]);
    }
}

// ---------------------------------------------------------------------------
// qk projection bf16x3 mma, cp.async double-buffered.
// C[4096][2048], K=1024. 128x128 tiles, 8 warps (4x2), warp m32xn64.
// Dynamic smem: 2 slabs x 4 arrays x [16][136].
// ---------------------------------------------------------------------------
#define SLAB 2176                     // 16*136 words per array
#define PROJ_SMEM (2 * 4 * SLAB * 4)  // bytes

__device__ __forceinline__ void proj_load(uint32_t* buf, int k2b,
                                          int mb, int nb, int tid) {
    #pragma unroll
    for (int it = 0; it < 2; it++) {
        int idx = tid + it * 256;
        int r = idx >> 5, c4 = idx & 31;
        size_t ga = (size_t)(k2b + r) * 4096 + mb * 128 + c4 * 4;
        size_t gb = (size_t)(k2b + r) * 2048 + nb * 128 + c4 * 4;
        int so = r * 136 + c4 * 4;
        cp16(buf + so,            g_ah + ga);
        cp16(buf + SLAB + so,     g_al + ga);
        cp16(buf + 2*SLAB + so,   g_wh + gb);
        cp16(buf + 3*SLAB + so,   g_wl + gb);
    }
}

__global__ __launch_bounds__(256, 2)
void qk_proj_mma(const float* __restrict__ bias) {
    extern __shared__ uint32_t sm[];
    const int nb = blockIdx.x, mb = blockIdx.y;
    const int tid = threadIdx.x, lane = tid & 31, wid = tid >> 5;
    const int wm = (wid & 3) * 32, wn = (wid >> 2) * 64;
    const int lq = lane & 3, lr = lane >> 2;

    float acc[2][8][4] = {};

    proj_load(sm, 0, mb, nb, tid);
    CP_COMMIT();

    for (int ki = 0; ki < 32; ki++) {
        if (ki < 31) {
            proj_load(sm + ((ki + 1) & 1) * 4 * SLAB, (ki + 1) * 16, mb, nb, tid);
            CP_COMMIT();
            CP_WAIT1();
        } else {
            CP_WAIT0();
        }
        __syncthreads();
        uint32_t* Ah = sm + (ki & 1) * 4 * SLAB;
        uint32_t* Al = Ah + SLAB;
        uint32_t* Bh = Ah + 2 * SLAB;
        uint32_t* Bl = Ah + 3 * SLAB;
        #pragma unroll
        for (int ks = 0; ks < 2; ks++) {
            const int kb = ks * 8;
            uint32_t ah[2][4], al_[2][4];
            #pragma unroll
            for (int mi = 0; mi < 2; mi++) {
                int rb = wm + mi * 16;
                ah[mi][0]  = Ah[(kb+lq)*136 + rb+lr];
                ah[mi][1]  = Ah[(kb+lq)*136 + rb+8+lr];
                ah[mi][2]  = Ah[(kb+4+lq)*136 + rb+lr];
                ah[mi][3]  = Ah[(kb+4+lq)*136 + rb+8+lr];
                al_[mi][0] = Al[(kb+lq)*136 + rb+lr];
                al_[mi][1] = Al[(kb+lq)*136 + rb+8+lr];
                al_[mi][2] = Al[(kb+4+lq)*136 + rb+lr];
                al_[mi][3] = Al[(kb+4+lq)*136 + rb+8+lr];
            }
            #pragma unroll
            for (int ni = 0; ni < 8; ni++) {
                int cb = wn + ni * 8 + lr;
                uint32_t bh0 = Bh[(kb+lq)*136 + cb], bh1 = Bh[(kb+4+lq)*136 + cb];
                uint32_t bl0 = Bl[(kb+lq)*136 + cb], bl1 = Bl[(kb+4+lq)*136 + cb];
                #pragma unroll
                for (int mi = 0; mi < 2; mi++) {
                    mma_bf16(acc[mi][ni], ah[mi],  bh0, bh1);
                    mma_bf16(acc[mi][ni], ah[mi],  bl0, bl1);
                    mma_bf16(acc[mi][ni], al_[mi], bh0, bh1);
                }
            }
        }
        __syncthreads();
    }

    #pragma unroll
    for (int mi = 0; mi < 2; mi++) {
        int m0 = mb * 128 + wm + mi * 16 + lr;
        int b = m0 >> 11, t = m0 & (TT - 1);
        #pragma unroll
        for (int ni = 0; ni < 8; ni++) {
            int n0 = nb * 128 + wn + ni * 8 + 2 * lq;
            float2 bv = *(const float2*)(bias + n0);
            int nn = n0 & (DD - 1);
            uint32_t* dh = (n0 < DD) ? g_qh : g_kh;
            uint32_t* dl = (n0 < DD) ? g_ql : g_kl;
            size_t base =
                ((size_t)((b*HH + (nn >> 6)) * 32 + ((nn & 63) >> 1))) * TT + t;
            uint32_t h, l;
            split2(acc[mi][ni][0] + bv.x, acc[mi][ni][1] + bv.y, h, l);
            dh[base] = h; dl[base] = l;
            split2(acc[mi][ni][2] + bv.x, acc[mi][ni][3] + bv.y, h, l);
            dh[base + 8] = h; dl[base + 8] = l;
        }
    }
}

// ---------------------------------------------------------------------------
// v head-mix -> key-pair-packed hi/lo v [bh][t2][d]. Block per (b, t-pair).
// ---------------------------------------------------------------------------
__global__ __launch_bounds__(256)
void mixv_kernel(const float* __restrict__ xt, const float* __restrict__ vf) {
    __shared__ float xs[2048];
    __shared__ float fs[256];
    const int bx = blockIdx.x;
    const int b = bx >> 10, tt2 = bx & 1023;
    const int tid = threadIdx.x;
    size_t row0 = ((size_t)(b * TT + tt2 * 2)) * DD;
    *(float4*)&xs[tid*4]        = *(const float4*)(xt + row0 + tid*4);
    *(float4*)&xs[1024 + tid*4] = *(const float4*)(xt + row0 + DD + tid*4);
    if (tid < 64) *(float4*)&fs[tid*4] = *(const float4*)(vf + tid*4);
    __syncthreads();

    const int o = tid * 4, i = o >> 6, d = o & 63;
    float4 a0 = make_float4(0.f,0.f,0.f,0.f);
    float4 a1 = make_float4(0.f,0.f,0.f,0.f);
    #pragma unroll
    for (int j = 0; j < 16; j++) {
        float f = fs[i*16 + j];
        float4 x0 = *(const float4*)&xs[j*64 + d];
        float4 x1 = *(const float4*)&xs[1024 + j*64 + d];
        a0.x = fmaf(f, x0.x, a0.x); a0.y = fmaf(f, x0.y, a0.y);
        a0.z = fmaf(f, x0.z, a0.z); a0.w = fmaf(f, x0.w, a0.w);
        a1.x = fmaf(f, x1.x, a1.x); a1.y = fmaf(f, x1.y, a1.y);
        a1.z = fmaf(f, x1.z, a1.z); a1.w = fmaf(f, x1.w, a1.w);
    }
    uint4 uh, ul;
    split2(a0.x, a1.x, uh.x, ul.x);
    split2(a0.y, a1.y, uh.y, ul.y);
    split2(a0.z, a1.z, uh.z, ul.z);
    split2(a0.w, a1.w, uh.w, ul.w);
    size_t dst = ((size_t)((b*HH + i) * 1024 + tt2)) * 64 + d;
    *(uint4*)(g_vh + dst) = uh;
    *(uint4*)(g_vl + dst) = ul;
}

// ---------------------------------------------------------------------------
// causal flash attention, bf16x3 mma, ALiBi, cp.async double-buffered KV.
// Block = (qt, bh), q-tile 128, key-tile 64, 256 threads = 8 warps of m16n64.
// P stays in registers (S frag == PV A frag).
// smem: Qh/Ql [32][136] + 2 x (Kh,Kl,Vh,Vl)[32][72].
// ---------------------------------------------------------------------------
#define QW 4352                       // 32*136 words per Q array
#define KVA 2304                      // 32*72 words per KV array
#define KVS (4 * KVA)                 // words per KV slab
#define ATTN_SMEM ((2*QW + 2*KVS) * 4)

__device__ __forceinline__ void attn_load_kv(uint32_t* buf, int bh, int kt,
                                             int tid) {
    #pragma unroll
    for (int it = 0; it < 2; it++) {
        int idx = tid + it * 256;
        int r = idx >> 4, c4 = idx & 15;
        int so = r * 72 + c4 * 4;
        size_t gk = ((size_t)(bh * 32 + r)) * TT + kt * 64 + c4 * 4;
        size_t gv = ((size_t)(bh * 1024 + kt * 32 + r)) * 64 + c4 * 4;
        cp16(buf + so,           g_kh + gk);
        cp16(buf + KVA + so,     g_kl + gk);
        cp16(buf + 2*KVA + so,   g_vh + gv);
        cp16(buf + 3*KVA + so,   g_vl + gv);
    }
}

__global__ __launch_bounds__(256, 2)
void attn_mma() {
    extern __shared__ uint32_t sm[];
    uint32_t* Qh = sm;
    uint32_t* Ql = sm + QW;
    uint32_t* kvbase = sm + 2 * QW;

    const int qt = 15 - (int)blockIdx.x;     // heavy tiles first
    const int bh = blockIdx.y;
    const int h = bh & (HH - 1);
    const float slope = exp2f(-0.5f * (float)(h + 1));
    const int tid = threadIdx.x, lane = tid & 31, wid = tid >> 5;
    const int lq = lane & 3, lr = lane >> 2;
    const int qbase = qt * 128, wrow = wid * 16;

    // Q tile + KV slab 0 in one cp.async group
    #pragma unroll
    for (int it = 0; it < 4; it++) {
        int idx = tid + it * 256;
        int r = idx >> 5, c4 = idx & 31;
        size_t g = ((size_t)(bh * 32 + r)) * TT + qbase + c4 * 4;
        cp16(Qh + r*136 + c4*4, g_qh + g);
        cp16(Ql + r*136 + c4*4, g_ql + g);
    }
    attn_load_kv(kvbase, bh, 0, tid);
    CP_COMMIT();

    float o[8][4] = {};
    float m_st[2], l_st[2];
    m_st[0] = m_st[1] = -1e30f;
    l_st[0] = l_st[1] = 0.f;

    const int nkt = 2 * qt + 2;
    for (int kt = 0; kt < nkt; kt++) {
        if (kt < nkt - 1) {
            attn_load_kv(kvbase + ((kt + 1) & 1) * KVS, bh, kt + 1, tid);
            CP_COMMIT();
            CP_WAIT1();
        } else {
            CP_WAIT0();
        }
        __syncthreads();
        uint32_t* Kh = kvbase + (kt & 1) * KVS;
        uint32_t* Kl = Kh + KVA;
        uint32_t* Vh = Kh + 2 * KVA;
        uint32_t* Vl = Kh + 3 * KVA;

        // S = Q K^T
        float s[8][4] = {};
        #pragma unroll
        for (int ks = 0; ks < 4; ks++) {
            int kb = ks * 8;
            uint32_t qah[4], qal[4];
            qah[0] = Qh[(kb+lq)*136 + wrow+lr];
            qah[1] = Qh[(kb+lq)*136 + wrow+8+lr];
            qah[2] = Qh[(kb+4+lq)*136 + wrow+lr];
            qah[3] = Qh[(kb+4+lq)*136 + wrow+8+lr];
            qal[0] = Ql[(kb+lq)*136 + wrow+lr];
            qal[1] = Ql[(kb+lq)*136 + wrow+8+lr];
            qal[2] = Ql[(kb+4+lq)*136 + wrow+lr];
            qal[3] = Ql[(kb+4+lq)*136 + wrow+8+lr];
            #pragma unroll
            for (int nj = 0; nj < 8; nj++) {
                int cb = nj * 8 + lr;
                uint32_t kh0 = Kh[(kb+lq)*72 + cb], kh1 = Kh[(kb+4+lq)*72 + cb];
                uint32_t kl0 = Kl[(kb+lq)*72 + cb], kl1 = Kl[(kb+4+lq)*72 + cb];
                mma_bf16(s[nj], qah, kh0, kh1);
                mma_bf16(s[nj], qah, kl0, kl1);
                mma_bf16(s[nj], qal, kh0, kh1);
            }
        }

        // scale + ALiBi + causal mask + online softmax
        const bool partial = (kt >= 2 * qt);
        #pragma unroll
        for (int half = 0; half < 2; half++) {
            int qi = qbase + wrow + lr + half * 8;
            float tm = -1e30f;
            #pragma unroll
            for (int nj = 0; nj < 8; nj++) {
                #pragma unroll
                for (int c = 0; c < 2; c++) {
                    int ki = kt * 64 + nj * 8 + 2 * lq + c;
                    float v = fmaf(s[nj][half*2+c], 0.125f,
                                   slope * (float)(ki - qi));
                    if (partial && ki > qi) v = -1e30f;
                    s[nj][half*2+c] = v;
                    tm = fmaxf(tm, v);
                }
            }
            tm = fmaxf(tm, __shfl_xor_sync(0xffffffffu, tm, 1));
            tm = fmaxf(tm, __shfl_xor_sync(0xffffffffu, tm, 2));
            float mnew = fmaxf(m_st[half], tm);
            float alpha = fast_exp(m_st[half] - mnew);
            float rsum = 0.f;
            #pragma unroll
            for (int nj = 0; nj < 8; nj++) {
                #pragma unroll
                for (int c = 0; c < 2; c++) {
                    float p = fast_exp(s[nj][half*2+c] - mnew);
                    s[nj][half*2+c] = p;
                    rsum += p;
                }
            }
            rsum += __shfl_xor_sync(0xffffffffu, rsum, 1);
            rsum += __shfl_xor_sync(0xffffffffu, rsum, 2);
            l_st[half] = l_st[half] * alpha + rsum;
            m_st[half] = mnew;
            #pragma unroll
            for (int nj = 0; nj < 8; nj++) {
                o[nj][half*2+0] *= alpha;
                o[nj][half*2+1] *= alpha;
            }
        }

        // O += P V
        #pragma unroll
        for (int ks = 0; ks < 4; ks++) {
            int kb = ks * 8;
            uint32_t ph[4], pl[4];
            split2(s[2*ks][0],   s[2*ks][1],   ph[0], pl[0]);
            split2(s[2*ks][2],   s[2*ks][3],   ph[1], pl[1]);
            split2(s[2*ks+1][0], s[2*ks+1][1], ph[2], pl[2]);
            split2(s[2*ks+1][2], s[2*ks+1][3], ph[3], pl[3]);
            #pragma unroll
            for (int nj = 0; nj < 8; nj++) {
                int cb = nj * 8 + lr;
                uint32_t vh0 = Vh[(kb+lq)*72 + cb], vh1 = Vh[(kb+4+lq)*72 + cb];
                uint32_t vl0 = Vl[(kb+lq)*72 + cb], vl1 = Vl[(kb+4+lq)*72 + cb];
                mma_bf16(o[nj], ph, vh0, vh1);
                mma_bf16(o[nj], ph, vl0, vl1);
                mma_bf16(o[nj], pl, vh0, vh1);
            }
        }
        __syncthreads();
    }

    // epilogue: normalize, write g_y (b,t,h,d)
    const int b = bh >> 4;
    #pragma unroll
    for (int half = 0; half < 2; half++) {
        int qi = qbase + wrow + lr + half * 8;
        float inv = 1.0f / l_st[half];
        #pragma unroll
        for (int nj = 0; nj < 8; nj++) {
            float2 w = make_float2(o[nj][half*2] * inv,
                                   o[nj][half*2+1] * inv);
            *(float2*)(g_y + ((size_t)((b*TT + qi)*HH + h))*HD
                       + nj*8 + 2*lq) = w;
        }
    }
}

// ---------------------------------------------------------------------------
// final head-mix: out[b,t,i,d] = sum_j g_y[b,t,j,d]*of[i,j]
// ---------------------------------------------------------------------------
__global__ __launch_bounds__(256)
void mix_out(const float* __restrict__ fact, float* __restrict__ dst) {
    __shared__ float xs[1024];
    __shared__ float fs[256];
    const int bt = blockIdx.x;
    const int tid = threadIdx.x;
    *(float4*)&xs[tid*4] = *(const float4*)(g_y + (size_t)bt * 1024 + tid*4);
    if (tid < 64) *(float4*)&fs[tid*4] = *(const float4*)(fact + tid*4);
    __syncthreads();
    const int o = tid * 4, i = o >> 6, d = o & 63;
    float4 acc = make_float4(0.f,0.f,0.f,0.f);
    #pragma unroll
    for (int j = 0; j < 16; j++) {
        float f = fs[i*16 + j];
        float4 x = *(const float4*)&xs[j*64 + d];
        acc.x = fmaf(f, x.x, acc.x); acc.y = fmaf(f, x.y, acc.y);
        acc.z = fmaf(f, x.z, acc.z); acc.w = fmaf(f, x.w, acc.w);
    }
    *(float4*)(dst + (size_t)bt * 1024 + o) = acc;
}

// ---------------------------------------------------------------------------
extern "C" void kernel_launch(void* const* d_in, const int* in_sizes, int n_in,
                              void* d_out, int out_size) {
    const float* x_norm   = (const float*)d_in[0];
    const float* xt       = (const float*)d_in[1];
    const float* qk_w     = (const float*)d_in[2];
    const float* qk_b     = (const float*)d_in[3];
    const float* v_fact   = (const float*)d_in[4];
    const float* out_fact = (const float*)d_in[5];
    float* out = (float*)d_out;

    uint32_t *p_ah, *p_al, *p_wh, *p_wl;
    cudaGetSymbolAddress((void**)&p_ah, g_ah);
    cudaGetSymbolAddress((void**)&p_al, g_al);
    cudaGetSymbolAddress((void**)&p_wh, g_wh);
    cudaGetSymbolAddress((void**)&p_wl, g_wl);
    cudaFuncSetAttribute(qk_proj_mma,
        cudaFuncAttributeMaxDynamicSharedMemorySize, PROJ_SMEM);
    cudaFuncSetAttribute(attn_mma,
        cudaFuncAttributeMaxDynamicSharedMemorySize, ATTN_SMEM);

    pack_kernel<<<dim3(16, 128), 256>>>(x_norm, p_ah, p_al, 4096);
    pack_kernel<<<dim3(16, 64),  256>>>(qk_w,   p_wh, p_wl, 2048);
    mixv_kernel<<<2048, 256>>>(xt, v_fact);
    qk_proj_mma<<<dim3(16, 32), 256, PROJ_SMEM>>>(qk_b);
    attn_mma<<<dim3(16, 32), 256, ATTN_SMEM>>>();
    mix_out<<<BB*TT, 256>>>(out_fact, out);
}